// round 14
// baseline (speedup 1.0000x reference)
#include <cuda_runtime.h>
#include <cuda_bf16.h>
#include <cstdint>

#define NB 4

// ------------------------- static scratch buffers --------------------------
static __device__ float g_up5 [4u * 256u * 32u * 32u];
static __device__ float g_off5[4u * 256u * 32u * 32u];
static __device__ float g_om5 [4u * 216u * 32u * 32u];
static __device__ float g_col [4u * 2304u * 64u * 64u];
static __device__ float g_al5 [4u * 256u * 32u * 32u];
static __device__ float g_c1b [4u * 256u * 32u * 32u];
static __device__ float g_up4 [4u * 256u * 64u * 64u];
static __device__ float g_off4[4u * 256u * 64u * 64u];
static __device__ float g_om4 [4u * 216u * 64u * 64u];
static __device__ float g_al4 [4u * 256u * 64u * 64u];
static __device__ float g_f2  [4u * 512u * 128u * 128u];
static __device__ float g_mm  [4u * 2u * 128u * 128u];
static __device__ float g_sab [4u * 128u * 128u];
static __device__ float g_y   [4u * 256u * 128u * 128u];
static __device__ float g_st  [256];
// pre-split weights: [hi(256*K) | lo(256*K)] bf16, M zero-padded to 256
static __device__ __align__(16) __nv_bfloat16 g_wp[5767168];
#define WP_OFF5 0u
#define WP_OM5  262144u
#define WP_DCN5 1441792u
#define WP_C1   2621440u
#define WP_OFF4 2883584u
#define WP_OM4  3145728u
#define WP_DCN4 4325376u
#define WP_SEM  5505024u

__device__ __forceinline__ uint32_t smem_to_u32(const void* p) {
    uint32_t a;
    asm("{ .reg .u64 t; cvta.to.shared.u64 t, %1; cvt.u32.u64 %0, t; }"
        : "=r"(a) : "l"(p));
    return a;
}

// ---------------------------------------------------------------------------
// Weight prep: W[M][K] fp32 -> out[0..256*K) = hi bf16, out[256*K..) = lo bf16
// ---------------------------------------------------------------------------
__global__ __launch_bounds__(256)
void prep_w_kernel(const float* __restrict__ W, __nv_bfloat16* __restrict__ out,
                   int M, int K)
{
    int idx = blockIdx.x * 256 + threadIdx.x;
    if (idx >= 256 * K) return;
    int m = idx / K, k = idx - m * K;
    float v = (m < M) ? W[(size_t)m * K + k] : 0.f;
    __nv_bfloat16 hi = __float2bfloat16(v);
    __nv_bfloat16 lo = __float2bfloat16(v - __bfloat162float(hi));
    out[idx] = hi;
    out[(size_t)256 * K + idx] = lo;
}

// X loader modes: 0 plain [K][N], 1 concat(+scale), 2 im2col3x3 pad1, 3 (1+sa)
template<int MODE>
__device__ __forceinline__ float loadX(const float* __restrict__ X0,
                                       const float* __restrict__ X1,
                                       const float* __restrict__ sa,
                                       int b, int k, int p,
                                       int K, int N, int Csplit, float scale1,
                                       int Hin, int Win)
{
    if (MODE == 0) return X0[((size_t)b * K + k) * N + p];
    else if (MODE == 1) {
        if (k < Csplit) return X0[((size_t)b * Csplit + k) * N + p];
        return scale1 * X1[((size_t)b * (K - Csplit) + (k - Csplit)) * N + p];
    } else if (MODE == 2) {
        int cin = k / 9, t = k - cin * 9;
        int hh = p / Win + (t / 3) - 1;
        int ww = (p - (p / Win) * Win) + (t - (t / 3) * 3) - 1;
        if ((unsigned)hh < (unsigned)Hin && (unsigned)ww < (unsigned)Win)
            return X0[(((size_t)b * (K / 9) + cin) * Hin + hh) * Win + ww];
        return 0.f;
    } else return X0[((size_t)b * K + k) * N + p] * (1.f + sa[(size_t)b * N + p]);
}

__device__ __forceinline__ void mma_bf16(float* c, const unsigned* a, const unsigned* b)
{
    asm volatile(
        "mma.sync.aligned.m16n8k16.row.col.f32.bf16.bf16.f32 "
        "{%0,%1,%2,%3}, {%4,%5,%6,%7}, {%8,%9}, {%0,%1,%2,%3};"
        : "+f"(c[0]), "+f"(c[1]), "+f"(c[2]), "+f"(c[3])
        : "r"(a[0]), "r"(a[1]), "r"(a[2]), "r"(a[3]), "r"(b[0]), "r"(b[1]));
}
#define LDSM_X4(R, addr) \
    asm volatile("ldmatrix.sync.aligned.m8n8.x4.shared.b16 {%0,%1,%2,%3}, [%4];" \
        : "=r"((R)[0]), "=r"((R)[1]), "=r"((R)[2]), "=r"((R)[3]) : "r"(addr))

__device__ __forceinline__ unsigned bf2(__nv_bfloat16 a, __nv_bfloat16 b)
{
    return (unsigned)__bfloat16_as_ushort(a) | ((unsigned)__bfloat16_as_ushort(b) << 16);
}

// Swizzled row/unit -> byte offset within a tile plane (rows of 80 B; unit
// XORed with (row>>3)&3 so 8-row-congruent lanes hit distinct banks).
__device__ __forceinline__ uint32_t swz(int row, int unit)
{
    return (uint32_t)(row * 80 + ((unit ^ ((row >> 3) & 3)) << 4));
}

// ---------------------------------------------------------------------------
// mma.sync bf16 split GEMM, pipelined + swizzled smem + full-M option:
//  MB = 128 or 256 rows per CTA (weights padded to 256; MB=256 -> X built ONCE)
//  A via cp.async double-buffered; X prefetched to regs during compute.
//  Block MB(M) x BN(N), BK=32, 256 thr (8 warps = 4M x 2N).
//  acc += Ah*Xh + Ah*Xl + Al*Xh  (fp32 accum; error-free to ~2^-16).
// ---------------------------------------------------------------------------
template<int MODE, int BN, int MB>
__global__ __launch_bounds__(256, 2)
void gemm_mma_kernel(const __nv_bfloat16* __restrict__ Wp,
                     const float* __restrict__ X0, const float* __restrict__ X1,
                     const float* __restrict__ bias, const float* __restrict__ sa,
                     float* __restrict__ out,
                     int M, int K, int N, int Csplit, float scale1,
                     int Hin, int Win, int relu)
{
    constexpr int WM  = MB / 4;        // warp M tile
    constexpr int NI  = MB / 64;       // 16-row mma tiles per warp (i loop)
    constexpr int WN  = BN / 2;
    constexpr int JT  = BN / 16;
    constexpr int JP  = JT / 2;
    constexpr int KPT = BN / 8;        // k elems per thread in X fill
    constexpr int RR  = KPT / 2;
    constexpr int A_PLANE = MB * 80, A_BUF = 2 * A_PLANE;
    constexpr int X_PLANE = BN * 80, X_BUF = 2 * X_PLANE, X_BASE = 2 * A_BUF;
    constexpr int AITERS = MB / 32;

    extern __shared__ char smem[];
    const uint32_t su = smem_to_u32(smem);

    const int tid = threadIdx.x;
    const int wid = tid >> 5, lane = tid & 31;
    const int warp_m = wid & 3;
    const int warp_n = wid >> 2;
    const int lq = lane >> 2;
    const int lr = lane & 3;
    const int m0 = blockIdx.y * MB;
    const int n0 = blockIdx.x * BN;
    const int b  = blockIdx.z;
    const int NC = K / 32;
    const size_t loStride = (size_t)256 * K;

    float acc[NI][JT][4];
#pragma unroll
    for (int i = 0; i < NI; i++)
#pragma unroll
        for (int j = 0; j < JT; j++)
#pragma unroll
            for (int q = 0; q < 4; q++) acc[i][j][q] = 0.f;

    const int ar = lane & 7, aj = lane >> 3;

    auto prefA = [&](int c, int buf) {
        uint32_t sb = su + (uint32_t)buf * A_BUF;
#pragma unroll
        for (int r = 0; r < AITERS; r++) {
            int idx = tid + r * 256;
            int plane = idx / (MB * 4);
            int rem = idx % (MB * 4);
            int m = rem % MB, q = rem / MB;
            const __nv_bfloat16* g = Wp + (size_t)plane * loStride
                                   + (size_t)(m0 + m) * K + c * 32 + q * 8;
            uint32_t d = sb + (uint32_t)plane * A_PLANE + swz(m, q);
            asm volatile("cp.async.cg.shared.global [%0], [%1], 16;" :: "r"(d), "l"(g));
        }
        asm volatile("cp.async.commit_group;");
    };

    const int xn = tid % BN, xkh = tid / BN;
    auto prefX = [&](int c, float* xv) {
#pragma unroll
        for (int rr = 0; rr < RR; rr++) {
            int k = c * 32 + xkh * KPT + rr * 2;
            xv[rr * 2]     = loadX<MODE>(X0, X1, sa, b, k,     n0 + xn, K, N, Csplit, scale1, Hin, Win);
            xv[rr * 2 + 1] = loadX<MODE>(X0, X1, sa, b, k + 1, n0 + xn, K, N, Csplit, scale1, Hin, Win);
        }
    };
    auto storeX = [&](const float* xv, int buf) {
        unsigned* Xh32 = (unsigned*)(smem + X_BASE + buf * X_BUF);
        unsigned* Xl32 = (unsigned*)(smem + X_BASE + buf * X_BUF + X_PLANE);
        int swzbase = (xn >> 3) & 3;
#pragma unroll
        for (int rr = 0; rr < RR; rr++) {
            int kl = xkh * KPT + rr * 2;
            float v0 = xv[rr * 2], v1 = xv[rr * 2 + 1];
            __nv_bfloat16 h0 = __float2bfloat16(v0), h1 = __float2bfloat16(v1);
            __nv_bfloat16 l0 = __float2bfloat16(v0 - __bfloat162float(h0));
            __nv_bfloat16 l1 = __float2bfloat16(v1 - __bfloat162float(h1));
            int u = kl >> 3;
            int idx32 = xn * 20 + (((u ^ swzbase) << 2) | ((kl >> 1) & 3));
            Xh32[idx32] = bf2(h0, h1);
            Xl32[idx32] = bf2(l0, l1);
        }
    };

    auto compute = [&](int buf) {
        uint32_t aB = su + (uint32_t)buf * A_BUF;
        uint32_t xB = su + X_BASE + (uint32_t)buf * X_BUF;
#pragma unroll
        for (int ks = 0; ks < 2; ks++) {
            unsigned bh[JP][4], bl[JP][4];
#pragma unroll
            for (int jp = 0; jp < JP; jp++) {
                int brow = warp_n * WN + jp * 16 + (aj >> 1) * 8 + ar;
                int bunit = (aj & 1) + ks * 2;
                LDSM_X4(bh[jp], xB + swz(brow, bunit));
                LDSM_X4(bl[jp], xB + X_PLANE + swz(brow, bunit));
            }
#pragma unroll
            for (int i = 0; i < NI; i++) {
                unsigned ah[4], al[4];
                int arow = warp_m * WM + i * 16 + ar + (aj & 1) * 8;
                int aunit = (aj >> 1) + ks * 2;
                LDSM_X4(ah, aB + swz(arow, aunit));
                LDSM_X4(al, aB + A_PLANE + swz(arow, aunit));
#pragma unroll
                for (int jp = 0; jp < JP; jp++)
#pragma unroll
                    for (int jo = 0; jo < 2; jo++) {
                        int j = jp * 2 + jo;
                        mma_bf16(acc[i][j], ah, bh[jp] + jo * 2);
                        mma_bf16(acc[i][j], ah, bl[jp] + jo * 2);
                        mma_bf16(acc[i][j], al, bh[jp] + jo * 2);
                    }
            }
        }
    };

    float xv[KPT];
    prefA(0, 0);
    prefX(0, xv);
    storeX(xv, 0);
    asm volatile("cp.async.wait_group 0;");
    __syncthreads();

    for (int c = 0; c < NC; c++) {
        int cur = c & 1;
        bool more = (c + 1 < NC);
        if (more) {
            prefA(c + 1, cur ^ 1);
            prefX(c + 1, xv);
        }
        compute(cur);
        if (more) {
            storeX(xv, cur ^ 1);
            asm volatile("cp.async.wait_group 0;");
        }
        __syncthreads();
    }

    // ---- epilogue ----
#pragma unroll
    for (int i = 0; i < NI; i++) {
        int row0 = m0 + warp_m * WM + i * 16 + lq;
        int row1 = row0 + 8;
        float bv0 = 0.f, bv1 = 0.f;
        if (bias) {
            if (row0 < M) bv0 = bias[row0];
            if (row1 < M) bv1 = bias[row1];
        }
#pragma unroll
        for (int j = 0; j < JT; j++) {
            int col = n0 + warp_n * WN + j * 8 + lr * 2;
            float2 o0, o1;
            o0.x = acc[i][j][0] + bv0; o0.y = acc[i][j][1] + bv0;
            o1.x = acc[i][j][2] + bv1; o1.y = acc[i][j][3] + bv1;
            if (relu) {
                o0.x = fmaxf(o0.x, 0.f); o0.y = fmaxf(o0.y, 0.f);
                o1.x = fmaxf(o1.x, 0.f); o1.y = fmaxf(o1.y, 0.f);
            }
            if (row0 < M)
                *(float2*)&out[((size_t)b * M + row0) * N + col] = o0;
            if (row1 < M)
                *(float2*)&out[((size_t)b * M + row1) * N + col] = o1;
        }
    }
}

#define SMEM_M128 61440
#define SMEM_M256 102400

// ------------------------- elementwise kernels -----------------------------
__global__ __launch_bounds__(256)
void upsample2x_kernel(const float* __restrict__ src0,
                       const float* __restrict__ src1,
                       int Csplit, int C, int Hin, int Win,
                       float* __restrict__ dst)
{
    const int Hout = Hin * 2, Wout = Win * 2;
    const long total = (long)NB * C * Hout * Wout;
    long idx = (long)blockIdx.x * blockDim.x + threadIdx.x;
    if (idx >= total) return;
    int x = (int)(idx % Wout);
    int y = (int)((idx / Wout) % Hout);
    int c = (int)((idx / ((long)Wout * Hout)) % C);
    int b = (int)(idx / ((long)Wout * Hout * C));
    float sy = y * 0.5f - 0.25f, sx = x * 0.5f - 0.25f;
    float y0f = floorf(sy), x0f = floorf(sx);
    float fy = sy - y0f, fx = sx - x0f;
    int y0 = (int)y0f, x0 = (int)x0f;
    int y0c = min(max(y0, 0), Hin - 1), y1c = min(max(y0 + 1, 0), Hin - 1);
    int x0c = min(max(x0, 0), Win - 1), x1c = min(max(x0 + 1, 0), Win - 1);
    const float* s = (c < Csplit)
        ? src0 + (size_t)(b * Csplit + c) * Hin * Win
        : src1 + (size_t)(b * (C - Csplit) + (c - Csplit)) * Hin * Win;
    float v00 = s[y0c * Win + x0c], v01 = s[y0c * Win + x1c];
    float v10 = s[y1c * Win + x0c], v11 = s[y1c * Win + x1c];
    dst[idx] = (1.f - fy) * ((1.f - fx) * v00 + fx * v01)
             +         fy * ((1.f - fx) * v10 + fx * v11);
}

__global__ __launch_bounds__(256)
void dcn_sample_kernel(const float* __restrict__ x, const float* __restrict__ om,
                       float* __restrict__ col, int H, int W)
{
    const int HW = H * W;
    const int total = NB * 72 * HW;
    int idx = blockIdx.x * blockDim.x + threadIdx.x;
    if (idx >= total) return;
    int p = idx % HW, gk = (idx / HW) % 72, b = idx / (72 * HW);
    int g = gk / 9, k = gk - g * 9;
    int h = p / W, w = p - h * W;
    float offy = om[((size_t)b * 216 +       gk) * HW + p];
    float offx = om[((size_t)b * 216 + 72 +  gk) * HW + p];
    float mraw = om[((size_t)b * 216 + 144 + gk) * HW + p];
    float msk = 1.f / (1.f + expf(-mraw));
    float yy = (float)h + (float)(k / 3 - 1) + offy;
    float xx = (float)w + (float)(k % 3 - 1) + offx;
    yy = fminf(fmaxf(yy, -1.0e6f), 1.0e6f);
    xx = fminf(fmaxf(xx, -1.0e6f), 1.0e6f);
    float y0f = floorf(yy), x0f = floorf(xx);
    int y0 = (int)y0f, x0 = (int)x0f;
    float fy = yy - y0f, fx = xx - x0f;
    bool vy0 = (y0 >= 0) && (y0 < H), vy1 = (y0 + 1 >= 0) && (y0 + 1 < H);
    bool vx0 = (x0 >= 0) && (x0 < W), vx1 = (x0 + 1 >= 0) && (x0 + 1 < W);
    int cy0 = min(max(y0, 0), H - 1), cy1 = min(max(y0 + 1, 0), H - 1);
    int cx0 = min(max(x0, 0), W - 1), cx1 = min(max(x0 + 1, 0), W - 1);
    float w00 = (vy0 && vx0) ? (1.f - fy) * (1.f - fx) * msk : 0.f;
    float w01 = (vy0 && vx1) ? (1.f - fy) * fx * msk : 0.f;
    float w10 = (vy1 && vx0) ? fy * (1.f - fx) * msk : 0.f;
    float w11 = (vy1 && vx1) ? fy * fx * msk : 0.f;
    int i00 = cy0 * W + cx0, i01 = cy0 * W + cx1;
    int i10 = cy1 * W + cx0, i11 = cy1 * W + cx1;
    const float* xb = x + (size_t)(b * 256 + g * 32) * HW;
    float* cb = col + ((size_t)b * 2304 + (size_t)(g * 32) * 9 + k) * HW + p;
#pragma unroll 4
    for (int c = 0; c < 32; c++) {
        const float* xc = xb + (size_t)c * HW;
        float v = w00 * xc[i00] + w01 * xc[i01] + w10 * xc[i10] + w11 * xc[i11];
        cb[(size_t)c * 9 * HW] = v;
    }
}

__global__ __launch_bounds__(256)
void meanmax_kernel(const float* __restrict__ f2, float* __restrict__ mm)
{
    int p = blockIdx.x * blockDim.x + threadIdx.x;
    int b = blockIdx.y;
    if (p >= 16384) return;
    const float* base = f2 + (size_t)b * 512 * 16384 + p;
    float s = 0.f, mx = -3.402823466e38f;
    for (int c = 0; c < 512; c++) {
        float v = base[(size_t)c * 16384];
        s += v;
        mx = fmaxf(mx, v);
    }
    mm[((size_t)b * 2 + 0) * 16384 + p] = s * (1.f / 512.f);
    mm[((size_t)b * 2 + 1) * 16384 + p] = mx;
}

__global__ __launch_bounds__(256)
void sa_kernel(const float* __restrict__ mm, const float* __restrict__ wsa,
               const float* __restrict__ bng, const float* __restrict__ bnb,
               const float* __restrict__ bnm, const float* __restrict__ bnv,
               float* __restrict__ sa)
{
    int p = blockIdx.x * blockDim.x + threadIdx.x;
    int b = blockIdx.y;
    if (p >= 16384) return;
    int y = p >> 7, x = p & 127;
    float acc = 0.f;
#pragma unroll
    for (int ic = 0; ic < 2; ic++) {
        const float* src = mm + ((size_t)b * 2 + ic) * 16384;
        const float* wk = wsa + ic * 49;
#pragma unroll
        for (int ky = 0; ky < 7; ky++) {
            int yy = y + ky - 3;
            if ((unsigned)yy >= 128u) continue;
#pragma unroll
            for (int kx = 0; kx < 7; kx++) {
                int xx = x + kx - 3;
                if ((unsigned)xx >= 128u) continue;
                acc += src[yy * 128 + xx] * wk[ky * 7 + kx];
            }
        }
    }
    float a = (acc - bnm[0]) * rsqrtf(bnv[0] + 1e-5f) * bng[0] + bnb[0];
    sa[(size_t)b * 16384 + p] = 1.f / (1.f + expf(-a));
}

__global__ __launch_bounds__(256)
void gn_reduce_kernel(const float* __restrict__ y, float* __restrict__ stats)
{
    const int bg = blockIdx.x;
    const float* base = y + (size_t)bg * 8 * 16384;
    float s = 0.f, sq = 0.f;
    for (int i = threadIdx.x; i < 8 * 16384; i += 256) {
        float v = base[i];
        s += v;
        sq += v * v;
    }
    __shared__ float ss[256], ssq[256];
    ss[threadIdx.x] = s;
    ssq[threadIdx.x] = sq;
    __syncthreads();
    for (int st = 128; st > 0; st >>= 1) {
        if (threadIdx.x < st) {
            ss[threadIdx.x] += ss[threadIdx.x + st];
            ssq[threadIdx.x] += ssq[threadIdx.x + st];
        }
        __syncthreads();
    }
    if (threadIdx.x == 0) {
        const float inv = 1.f / (8.f * 16384.f);
        float mean = ss[0] * inv;
        float var = ssq[0] * inv - mean * mean;
        stats[bg * 2 + 0] = mean;
        stats[bg * 2 + 1] = rsqrtf(var + 1e-5f);
    }
}

__global__ __launch_bounds__(256)
void gn_apply_kernel(const float* __restrict__ y, const float* __restrict__ stats,
                     const float* __restrict__ gg, const float* __restrict__ gb,
                     float* __restrict__ out)
{
    size_t idx = (size_t)blockIdx.x * blockDim.x + threadIdx.x;
    if (idx >= (size_t)16777216) return;
    int c = (int)((idx >> 14) & 255);
    int b = (int)(idx >> 22);
    int g = c >> 3;
    float mean = stats[(b * 32 + g) * 2 + 0];
    float rstd = stats[(b * 32 + g) * 2 + 1];
    out[idx] = (y[idx] - mean) * rstd * gg[c] + gb[c];
}

// ------------------------------ host ---------------------------------------
static void* symaddr(const void* sym)
{
    void* p = nullptr;
    cudaGetSymbolAddress(&p, sym);
    return p;
}

extern "C" void kernel_launch(void* const* d_in, const int* in_sizes, int n_in,
                              void* d_out, int out_size)
{
    (void)in_sizes; (void)n_in; (void)out_size;
    const float* feat_3 = (const float*)d_in[1];
    const float* feat_4 = (const float*)d_in[2];
    const float* feat_5 = (const float*)d_in[3];
    const float* w_off5 = (const float*)d_in[4];
    const float* w_om5  = (const float*)d_in[5];
    const float* b_om5  = (const float*)d_in[6];
    const float* w_dcn5 = (const float*)d_in[7];
    const float* b_dcn5 = (const float*)d_in[8];
    const float* w_c1   = (const float*)d_in[9];
    const float* w_off4 = (const float*)d_in[10];
    const float* w_om4  = (const float*)d_in[11];
    const float* b_om4  = (const float*)d_in[12];
    const float* w_dcn4 = (const float*)d_in[13];
    const float* b_dcn4 = (const float*)d_in[14];
    const float* w_sa   = (const float*)d_in[15];
    const float* bn_g   = (const float*)d_in[16];
    const float* bn_b   = (const float*)d_in[17];
    const float* bn_m   = (const float*)d_in[18];
    const float* bn_v   = (const float*)d_in[19];
    const float* w_sem  = (const float*)d_in[20];
    const float* gn_g   = (const float*)d_in[21];
    const float* gn_b   = (const float*)d_in[22];
    float* out = (float*)d_out;

    float* up5  = (float*)symaddr(g_up5);
    float* off5 = (float*)symaddr(g_off5);
    float* om5  = (float*)symaddr(g_om5);
    float* col  = (float*)symaddr(g_col);
    float* al5  = (float*)symaddr(g_al5);
    float* c1b  = (float*)symaddr(g_c1b);
    float* up4  = (float*)symaddr(g_up4);
    float* off4 = (float*)symaddr(g_off4);
    float* om4  = (float*)symaddr(g_om4);
    float* al4  = (float*)symaddr(g_al4);
    float* f2   = (float*)symaddr(g_f2);
    float* mm   = (float*)symaddr(g_mm);
    float* sab  = (float*)symaddr(g_sab);
    float* ybuf = (float*)symaddr(g_y);
    float* st   = (float*)symaddr(g_st);
    __nv_bfloat16* wp = (__nv_bfloat16*)symaddr(g_wp);

    cudaFuncSetAttribute(gemm_mma_kernel<0, 64, 128>, cudaFuncAttributeMaxDynamicSharedMemorySize, SMEM_M128);
    cudaFuncSetAttribute(gemm_mma_kernel<1, 64, 128>, cudaFuncAttributeMaxDynamicSharedMemorySize, SMEM_M128);
    cudaFuncSetAttribute(gemm_mma_kernel<2, 64, 128>, cudaFuncAttributeMaxDynamicSharedMemorySize, SMEM_M128);
    cudaFuncSetAttribute(gemm_mma_kernel<0, 64, 256>, cudaFuncAttributeMaxDynamicSharedMemorySize, SMEM_M256);
    cudaFuncSetAttribute(gemm_mma_kernel<1, 64, 256>, cudaFuncAttributeMaxDynamicSharedMemorySize, SMEM_M256);
    cudaFuncSetAttribute(gemm_mma_kernel<2, 64, 256>, cudaFuncAttributeMaxDynamicSharedMemorySize, SMEM_M256);
    cudaFuncSetAttribute(gemm_mma_kernel<3, 64, 256>, cudaFuncAttributeMaxDynamicSharedMemorySize, SMEM_M256);

    // ----- level 5 (16 -> 32): order puts the K=2304 im2col GEMM at #6 -----
    prep_w_kernel<<<512, 256>>>(w_off5, wp + WP_OFF5, 256, 512);    // 1
    prep_w_kernel<<<2304, 256>>>(w_om5,  wp + WP_OM5, 216, 2304);   // 2
    prep_w_kernel<<<2304, 256>>>(w_dcn5, wp + WP_DCN5, 256, 2304);  // 3
    upsample2x_kernel<<<(4 * 256 * 1024 + 255) / 256, 256>>>(       // 4
        feat_5, feat_5, 256, 256, 16, 16, up5);
    gemm_mma_kernel<1, 64, 128><<<dim3(16, 2, NB), 256, SMEM_M128>>>(  // 5
        wp + WP_OFF5, feat_4, up5, nullptr, nullptr, off5,
        256, 512, 1024, 256, 2.0f, 0, 0, 0);
    gemm_mma_kernel<2, 64, 128><<<dim3(16, 2, NB), 256, SMEM_M128>>>(  // 6 <- profile
        wp + WP_OM5, off5, nullptr, b_om5, nullptr, om5,
        216, 2304, 1024, 0, 0.f, 32, 32, 0);
    dcn_sample_kernel<<<(NB * 72 * 1024 + 255) / 256, 256>>>(up5, om5, col, 32, 32);
    gemm_mma_kernel<0, 64, 128><<<dim3(16, 2, NB), 256, SMEM_M128>>>(
        wp + WP_DCN5, col, nullptr, b_dcn5, nullptr, al5,
        256, 2304, 1024, 0, 0.f, 0, 0, 1);
    prep_w_kernel<<<512, 256>>>(w_c1, wp + WP_C1, 256, 512);
    gemm_mma_kernel<1, 64, 128><<<dim3(16, 2, NB), 256, SMEM_M128>>>(
        wp + WP_C1, al5, feat_4, nullptr, nullptr, c1b,
        256, 512, 1024, 256, 1.0f, 0, 0, 0);

    // ----- level 4 (32 -> 64), N=4096: MB=256 (X built once) -----
    prep_w_kernel<<<512, 256>>>(w_off4, wp + WP_OFF4, 256, 512);
    upsample2x_kernel<<<(4 * 256 * 4096 + 255) / 256, 256>>>(
        c1b, c1b, 256, 256, 32, 32, up4);
    gemm_mma_kernel<1, 64, 256><<<dim3(64, 1, NB), 256, SMEM_M256>>>(
        wp + WP_OFF4, feat_3, up4, nullptr, nullptr, off4,
        256, 512, 4096, 256, 2.0f, 0, 0, 0);
    prep_w_kernel<<<2304, 256>>>(w_om4, wp + WP_OM4, 216, 2304);
    gemm_mma_kernel<2, 64, 256><<<dim3(64, 1, NB), 256, SMEM_M256>>>(
        wp + WP_OM4, off4, nullptr, b_om4, nullptr, om4,
        216, 2304, 4096, 0, 0.f, 64, 64, 0);
    dcn_sample_kernel<<<(NB * 72 * 4096 + 255) / 256, 256>>>(up4, om4, col, 64, 64);
    prep_w_kernel<<<2304, 256>>>(w_dcn4, wp + WP_DCN4, 256, 2304);
    gemm_mma_kernel<0, 64, 256><<<dim3(64, 1, NB), 256, SMEM_M256>>>(
        wp + WP_DCN4, col, nullptr, b_dcn4, nullptr, al4,
        256, 2304, 4096, 0, 0.f, 0, 0, 1);

    // ----- feat_2 + SEM: MB=256 -----
    upsample2x_kernel<<<(unsigned)((4L * 512 * 16384 + 255) / 256), 256>>>(
        al4, feat_3, 256, 512, 64, 64, f2);
    prep_w_kernel<<<512, 256>>>(w_sem, wp + WP_SEM, 256, 512);
    meanmax_kernel<<<dim3(64, NB), 256>>>(f2, mm);
    sa_kernel<<<dim3(64, NB), 256>>>(mm, w_sa, bn_g, bn_b, bn_m, bn_v, sab);
    gemm_mma_kernel<3, 64, 256><<<dim3(256, 1, NB), 256, SMEM_M256>>>(
        wp + WP_SEM, f2, nullptr, nullptr, sab, ybuf,
        256, 512, 16384, 0, 0.f, 0, 0, 0);
    gn_reduce_kernel<<<128, 256>>>(ybuf, st);
    gn_apply_kernel<<<65536, 256>>>(ybuf, st, gn_g, gn_b, out);
}

// round 15
// speedup vs baseline: 1.0264x; 1.0264x over previous
#include <cuda_runtime.h>
#include <cuda_bf16.h>
#include <cstdint>

#define NB 4

// ------------------------- static scratch buffers --------------------------
static __device__ float    g_up5 [4u * 256u * 32u * 32u];
static __device__ float    g_om5 [4u * 216u * 32u * 32u];
static __device__ unsigned g_col [4u * 2304u * 64u * 64u];   // packed pairs
static __device__ float    g_c1b [4u * 256u * 32u * 32u];
static __device__ float    g_up4 [4u * 256u * 64u * 64u];
static __device__ float    g_om4 [4u * 216u * 64u * 64u];
static __device__ float    g_al4 [4u * 256u * 64u * 64u];
static __device__ float    g_f2  [4u * 512u * 128u * 128u];
static __device__ float    g_mm  [4u * 2u * 128u * 128u];
static __device__ float    g_sab [4u * 128u * 128u];
static __device__ float    g_y   [4u * 256u * 128u * 128u];
static __device__ float    g_st  [256];
// packed-pair (u32 = bf16 hi | bf16 lo << 16) X buffers
static __device__ unsigned g_f4p  [4u * 256u * 1024u];
static __device__ unsigned g_f3p  [4u * 256u * 4096u];
static __device__ unsigned g_up5p [4u * 256u * 1024u];
static __device__ unsigned g_al5p [4u * 256u * 1024u];
static __device__ unsigned g_up4p [4u * 256u * 4096u];
static __device__ unsigned g_off5p[4u * 256u * 1024u];
static __device__ unsigned g_off4p[4u * 256u * 4096u];
static __device__ unsigned g_f2sp [4u * 512u * 16384u];
// pre-split weights: [hi(256*K) | lo(256*K)] bf16, M zero-padded to 256
static __device__ __align__(16) __nv_bfloat16 g_wp[5767168];
#define WP_OFF5 0u
#define WP_OM5  262144u
#define WP_DCN5 1441792u
#define WP_C1   2621440u
#define WP_OFF4 2883584u
#define WP_OM4  3145728u
#define WP_DCN4 4325376u
#define WP_SEM  5505024u

__device__ __forceinline__ uint32_t smem_to_u32(const void* p) {
    uint32_t a;
    asm("{ .reg .u64 t; cvta.to.shared.u64 t, %1; cvt.u32.u64 %0, t; }"
        : "=r"(a) : "l"(p));
    return a;
}

__device__ __forceinline__ unsigned packsplit(float v)
{
    __nv_bfloat16 h = __float2bfloat16(v);
    __nv_bfloat16 l = __float2bfloat16(v - __bfloat162float(h));
    return (unsigned)__bfloat16_as_ushort(h)
         | ((unsigned)__bfloat16_as_ushort(l) << 16);
}

// ---------------------------------------------------------------------------
// Weight prep: W[M][K] fp32 (columns >= Cs scaled by sc — folds concat scale)
// -> out[0..256*K) = hi bf16, out[256*K..) = lo bf16
// ---------------------------------------------------------------------------
__global__ __launch_bounds__(256)
void prep_w_kernel(const float* __restrict__ W, __nv_bfloat16* __restrict__ out,
                   int M, int K, int Cs, float sc)
{
    int idx = blockIdx.x * 256 + threadIdx.x;
    if (idx >= 256 * K) return;
    int m = idx / K, k = idx - m * K;
    float v = (m < M) ? W[(size_t)m * K + k] : 0.f;
    if (k >= Cs) v *= sc;
    __nv_bfloat16 hi = __float2bfloat16(v);
    __nv_bfloat16 lo = __float2bfloat16(v - __bfloat162float(hi));
    out[idx] = hi;
    out[(size_t)256 * K + idx] = lo;
}

// fp32 -> packed-pair conversion (plain)
__global__ __launch_bounds__(256)
void conv_pair_kernel(const float* __restrict__ src, unsigned* __restrict__ dst,
                      int count)
{
    int idx = blockIdx.x * 256 + threadIdx.x;
    if (idx < count) dst[idx] = packsplit(src[idx]);
}

// f2 * (1 + sa) -> packed pairs (sem GEMM input)
__global__ __launch_bounds__(256)
void f2s_kernel(const float* __restrict__ f2, const float* __restrict__ sa,
                unsigned* __restrict__ dst)
{
    size_t idx = (size_t)blockIdx.x * 256 + threadIdx.x;
    if (idx >= (size_t)4 * 512 * 16384) return;
    int p = (int)(idx & 16383);
    int b = (int)(idx / ((size_t)512 * 16384));
    dst[idx] = packsplit(f2[idx] * (1.f + sa[(size_t)b * 16384 + p]));
}

// X loader (packed pairs): 0 plain [K][N], 1 concat, 2 im2col3x3 pad1
template<int MODE>
__device__ __forceinline__ unsigned loadX(const unsigned* __restrict__ X0,
                                          const unsigned* __restrict__ X1,
                                          int b, int k, int p,
                                          int K, int N, int Csplit,
                                          int Hin, int Win)
{
    if (MODE == 0) return X0[((size_t)b * K + k) * N + p];
    else if (MODE == 1) {
        if (k < Csplit) return X0[((size_t)b * Csplit + k) * N + p];
        return X1[((size_t)b * (K - Csplit) + (k - Csplit)) * N + p];
    } else {
        int cin = k / 9, t = k - cin * 9;
        int hh = p / Win + (t / 3) - 1;
        int ww = (p - (p / Win) * Win) + (t - (t / 3) * 3) - 1;
        if ((unsigned)hh < (unsigned)Hin && (unsigned)ww < (unsigned)Win)
            return X0[(((size_t)b * (K / 9) + cin) * Hin + hh) * Win + ww];
        return 0u;
    }
}

__device__ __forceinline__ void mma_bf16(float* c, const unsigned* a, const unsigned* b)
{
    asm volatile(
        "mma.sync.aligned.m16n8k16.row.col.f32.bf16.bf16.f32 "
        "{%0,%1,%2,%3}, {%4,%5,%6,%7}, {%8,%9}, {%0,%1,%2,%3};"
        : "+f"(c[0]), "+f"(c[1]), "+f"(c[2]), "+f"(c[3])
        : "r"(a[0]), "r"(a[1]), "r"(a[2]), "r"(a[3]), "r"(b[0]), "r"(b[1]));
}
#define LDSM_X4(R, addr) \
    asm volatile("ldmatrix.sync.aligned.m8n8.x4.shared.b16 {%0,%1,%2,%3}, [%4];" \
        : "=r"((R)[0]), "=r"((R)[1]), "=r"((R)[2]), "=r"((R)[3]) : "r"(addr))

// Swizzled row/unit -> byte offset (rows of 80 B; unit XORed with (row>>3)&3)
__device__ __forceinline__ uint32_t swz(int row, int unit)
{
    return (uint32_t)(row * 80 + ((unit ^ ((row >> 3) & 3)) << 4));
}

// ---------------------------------------------------------------------------
// mma.sync bf16 split GEMM (R13 structure), X pre-split as packed pairs:
//  prefX = plain u32 loads; storeX = PRMT regroup + STS (no float math).
//  A via cp.async double-buffered; 128(M) x BN(N) x BK=32, 256 thr.
//  acc += Ah*Xh + Ah*Xl + Al*Xh  (fp32 accum).
// ---------------------------------------------------------------------------
template<int MODE, int BN>
__global__ __launch_bounds__(256, 2)
void gemm_mma_kernel(const __nv_bfloat16* __restrict__ Wp,
                     const unsigned* __restrict__ X0,
                     const unsigned* __restrict__ X1,
                     const float* __restrict__ bias,
                     float* __restrict__ out, unsigned* __restrict__ pout,
                     int M, int K, int N, int Csplit,
                     int Hin, int Win, int relu)
{
    constexpr int WN  = BN / 2;
    constexpr int JT  = BN / 16;
    constexpr int JP  = JT / 2;
    constexpr int KPT = BN / 8;
    constexpr int RR  = KPT / 2;
    constexpr int A_PLANE = 10240, A_BUF = 20480;
    constexpr int X_PLANE = BN * 80, X_BUF = 2 * X_PLANE, X_BASE = 40960;

    extern __shared__ char smem[];
    const uint32_t su = smem_to_u32(smem);

    const int tid = threadIdx.x;
    const int wid = tid >> 5, lane = tid & 31;
    const int warp_m = wid & 3;
    const int warp_n = wid >> 2;
    const int lq = lane >> 2;
    const int lr = lane & 3;
    const int m0 = blockIdx.y * 128;
    const int n0 = blockIdx.x * BN;
    const int b  = blockIdx.z;
    const int NC = K / 32;
    const size_t loStride = (size_t)256 * K;

    float acc[2][JT][4];
#pragma unroll
    for (int i = 0; i < 2; i++)
#pragma unroll
        for (int j = 0; j < JT; j++)
#pragma unroll
            for (int q = 0; q < 4; q++) acc[i][j][q] = 0.f;

    const int ar = lane & 7, aj = lane >> 3;

    auto prefA = [&](int c, int buf) {
        uint32_t sb = su + (uint32_t)buf * A_BUF;
#pragma unroll
        for (int r = 0; r < 4; r++) {
            int idx = tid + r * 256;
            int plane = idx >> 9;
            int rem = idx & 511;
            int m = rem & 127, q = rem >> 7;
            const __nv_bfloat16* g = Wp + (size_t)plane * loStride
                                   + (size_t)(m0 + m) * K + c * 32 + q * 8;
            uint32_t d = sb + (uint32_t)plane * A_PLANE + swz(m, q);
            asm volatile("cp.async.cg.shared.global [%0], [%1], 16;" :: "r"(d), "l"(g));
        }
        asm volatile("cp.async.commit_group;");
    };

    const int xn = tid % BN, xkh = tid / BN;
    auto prefX = [&](int c, unsigned* xv) {
#pragma unroll
        for (int rr = 0; rr < RR; rr++) {
            int k = c * 32 + xkh * KPT + rr * 2;
            xv[rr * 2]     = loadX<MODE>(X0, X1, b, k,     n0 + xn, K, N, Csplit, Hin, Win);
            xv[rr * 2 + 1] = loadX<MODE>(X0, X1, b, k + 1, n0 + xn, K, N, Csplit, Hin, Win);
        }
    };
    auto storeX = [&](const unsigned* xv, int buf) {
        unsigned* Xh32 = (unsigned*)(smem + X_BASE + buf * X_BUF);
        unsigned* Xl32 = (unsigned*)(smem + X_BASE + buf * X_BUF + X_PLANE);
        int swzbase = (xn >> 3) & 3;
#pragma unroll
        for (int rr = 0; rr < RR; rr++) {
            int kl = xkh * KPT + rr * 2;
            unsigned p0 = xv[rr * 2], p1 = xv[rr * 2 + 1];
            int u = kl >> 3;
            int idx32 = xn * 20 + (((u ^ swzbase) << 2) | ((kl >> 1) & 3));
            Xh32[idx32] = __byte_perm(p0, p1, 0x5410);   // (hi0, hi1)
            Xl32[idx32] = __byte_perm(p0, p1, 0x7632);   // (lo0, lo1)
        }
    };

    auto compute = [&](int buf) {
        uint32_t aB = su + (uint32_t)buf * A_BUF;
        uint32_t xB = su + X_BASE + (uint32_t)buf * X_BUF;
#pragma unroll
        for (int ks = 0; ks < 2; ks++) {
            unsigned ah[2][4], al[2][4];
#pragma unroll
            for (int i = 0; i < 2; i++) {
                int arow = warp_m * 32 + i * 16 + ar + (aj & 1) * 8;
                int aunit = (aj >> 1) + ks * 2;
                LDSM_X4(ah[i], aB + swz(arow, aunit));
                LDSM_X4(al[i], aB + A_PLANE + swz(arow, aunit));
            }
#pragma unroll
            for (int jp = 0; jp < JP; jp++) {
                int brow = warp_n * WN + jp * 16 + (aj >> 1) * 8 + ar;
                int bunit = (aj & 1) + ks * 2;
                unsigned bh[4], bl[4];
                LDSM_X4(bh, xB + swz(brow, bunit));
                LDSM_X4(bl, xB + X_PLANE + swz(brow, bunit));
#pragma unroll
                for (int jo = 0; jo < 2; jo++) {
                    int j = jp * 2 + jo;
#pragma unroll
                    for (int i = 0; i < 2; i++) {
                        mma_bf16(acc[i][j], ah[i], bh + jo * 2);
                        mma_bf16(acc[i][j], ah[i], bl + jo * 2);
                        mma_bf16(acc[i][j], al[i], bh + jo * 2);
                    }
                }
            }
        }
    };

    unsigned xv[KPT];
    prefA(0, 0);
    prefX(0, xv);
    storeX(xv, 0);
    asm volatile("cp.async.wait_group 0;");
    __syncthreads();

    for (int c = 0; c < NC; c++) {
        int cur = c & 1;
        bool more = (c + 1 < NC);
        if (more) {
            prefA(c + 1, cur ^ 1);
            prefX(c + 1, xv);
        }
        compute(cur);
        if (more) {
            storeX(xv, cur ^ 1);
            asm volatile("cp.async.wait_group 0;");
        }
        __syncthreads();
    }

    // ---- epilogue: bias/relu, fp32 and/or packed-pair outputs ----
#pragma unroll
    for (int i = 0; i < 2; i++) {
        int row0 = m0 + warp_m * 32 + i * 16 + lq;
        int row1 = row0 + 8;
        float bv0 = 0.f, bv1 = 0.f;
        if (bias) {
            if (row0 < M) bv0 = bias[row0];
            if (row1 < M) bv1 = bias[row1];
        }
#pragma unroll
        for (int j = 0; j < JT; j++) {
            int col = n0 + warp_n * WN + j * 8 + lr * 2;
            float2 o0, o1;
            o0.x = acc[i][j][0] + bv0; o0.y = acc[i][j][1] + bv0;
            o1.x = acc[i][j][2] + bv1; o1.y = acc[i][j][3] + bv1;
            if (relu) {
                o0.x = fmaxf(o0.x, 0.f); o0.y = fmaxf(o0.y, 0.f);
                o1.x = fmaxf(o1.x, 0.f); o1.y = fmaxf(o1.y, 0.f);
            }
            if (out) {
                if (row0 < M)
                    *(float2*)&out[((size_t)b * M + row0) * N + col] = o0;
                if (row1 < M)
                    *(float2*)&out[((size_t)b * M + row1) * N + col] = o1;
            }
            if (pout) {
                if (row0 < M) {
                    uint2 q; q.x = packsplit(o0.x); q.y = packsplit(o0.y);
                    *(uint2*)&pout[((size_t)b * M + row0) * N + col] = q;
                }
                if (row1 < M) {
                    uint2 q; q.x = packsplit(o1.x); q.y = packsplit(o1.y);
                    *(uint2*)&pout[((size_t)b * M + row1) * N + col] = q;
                }
            }
        }
    }
}

#define SMEM128 81920
#define SMEM64  61440

// ------------------------- elementwise kernels -----------------------------
__global__ __launch_bounds__(256)
void upsample2x_kernel(const float* __restrict__ src0,
                       const float* __restrict__ src1,
                       int Csplit, int C, int Hin, int Win,
                       float* __restrict__ dst, unsigned* __restrict__ pdst)
{
    const int Hout = Hin * 2, Wout = Win * 2;
    const long total = (long)NB * C * Hout * Wout;
    long idx = (long)blockIdx.x * blockDim.x + threadIdx.x;
    if (idx >= total) return;
    int x = (int)(idx % Wout);
    int y = (int)((idx / Wout) % Hout);
    int c = (int)((idx / ((long)Wout * Hout)) % C);
    int b = (int)(idx / ((long)Wout * Hout * C));
    float sy = y * 0.5f - 0.25f, sx = x * 0.5f - 0.25f;
    float y0f = floorf(sy), x0f = floorf(sx);
    float fy = sy - y0f, fx = sx - x0f;
    int y0 = (int)y0f, x0 = (int)x0f;
    int y0c = min(max(y0, 0), Hin - 1), y1c = min(max(y0 + 1, 0), Hin - 1);
    int x0c = min(max(x0, 0), Win - 1), x1c = min(max(x0 + 1, 0), Win - 1);
    const float* s = (c < Csplit)
        ? src0 + (size_t)(b * Csplit + c) * Hin * Win
        : src1 + (size_t)(b * (C - Csplit) + (c - Csplit)) * Hin * Win;
    float v00 = s[y0c * Win + x0c], v01 = s[y0c * Win + x1c];
    float v10 = s[y1c * Win + x0c], v11 = s[y1c * Win + x1c];
    float v = (1.f - fy) * ((1.f - fx) * v00 + fx * v01)
            +         fy * ((1.f - fx) * v10 + fx * v11);
    if (dst)  dst[idx] = v;
    if (pdst) pdst[idx] = packsplit(v);
}

__global__ __launch_bounds__(256)
void dcn_sample_kernel(const float* __restrict__ x, const float* __restrict__ om,
                       unsigned* __restrict__ col, int H, int W)
{
    const int HW = H * W;
    const int total = NB * 72 * HW;
    int idx = blockIdx.x * blockDim.x + threadIdx.x;
    if (idx >= total) return;
    int p = idx % HW, gk = (idx / HW) % 72, b = idx / (72 * HW);
    int g = gk / 9, k = gk - g * 9;
    int h = p / W, w = p - h * W;
    float offy = om[((size_t)b * 216 +       gk) * HW + p];
    float offx = om[((size_t)b * 216 + 72 +  gk) * HW + p];
    float mraw = om[((size_t)b * 216 + 144 + gk) * HW + p];
    float msk = 1.f / (1.f + expf(-mraw));
    float yy = (float)h + (float)(k / 3 - 1) + offy;
    float xx = (float)w + (float)(k % 3 - 1) + offx;
    yy = fminf(fmaxf(yy, -1.0e6f), 1.0e6f);
    xx = fminf(fmaxf(xx, -1.0e6f), 1.0e6f);
    float y0f = floorf(yy), x0f = floorf(xx);
    int y0 = (int)y0f, x0 = (int)x0f;
    float fy = yy - y0f, fx = xx - x0f;
    bool vy0 = (y0 >= 0) && (y0 < H), vy1 = (y0 + 1 >= 0) && (y0 + 1 < H);
    bool vx0 = (x0 >= 0) && (x0 < W), vx1 = (x0 + 1 >= 0) && (x0 + 1 < W);
    int cy0 = min(max(y0, 0), H - 1), cy1 = min(max(y0 + 1, 0), H - 1);
    int cx0 = min(max(x0, 0), W - 1), cx1 = min(max(x0 + 1, 0), W - 1);
    float w00 = (vy0 && vx0) ? (1.f - fy) * (1.f - fx) * msk : 0.f;
    float w01 = (vy0 && vx1) ? (1.f - fy) * fx * msk : 0.f;
    float w10 = (vy1 && vx0) ? fy * (1.f - fx) * msk : 0.f;
    float w11 = (vy1 && vx1) ? fy * fx * msk : 0.f;
    int i00 = cy0 * W + cx0, i01 = cy0 * W + cx1;
    int i10 = cy1 * W + cx0, i11 = cy1 * W + cx1;
    const float* xb = x + (size_t)(b * 256 + g * 32) * HW;
    unsigned* cb = col + ((size_t)b * 2304 + (size_t)(g * 32) * 9 + k) * HW + p;
#pragma unroll 4
    for (int c = 0; c < 32; c++) {
        const float* xc = xb + (size_t)c * HW;
        float v = w00 * xc[i00] + w01 * xc[i01] + w10 * xc[i10] + w11 * xc[i11];
        cb[(size_t)c * 9 * HW] = packsplit(v);
    }
}

__global__ __launch_bounds__(256)
void meanmax_kernel(const float* __restrict__ f2, float* __restrict__ mm)
{
    int p = blockIdx.x * blockDim.x + threadIdx.x;
    int b = blockIdx.y;
    if (p >= 16384) return;
    const float* base = f2 + (size_t)b * 512 * 16384 + p;
    float s = 0.f, mx = -3.402823466e38f;
    for (int c = 0; c < 512; c++) {
        float v = base[(size_t)c * 16384];
        s += v;
        mx = fmaxf(mx, v);
    }
    mm[((size_t)b * 2 + 0) * 16384 + p] = s * (1.f / 512.f);
    mm[((size_t)b * 2 + 1) * 16384 + p] = mx;
}

__global__ __launch_bounds__(256)
void sa_kernel(const float* __restrict__ mm, const float* __restrict__ wsa,
               const float* __restrict__ bng, const float* __restrict__ bnb,
               const float* __restrict__ bnm, const float* __restrict__ bnv,
               float* __restrict__ sa)
{
    int p = blockIdx.x * blockDim.x + threadIdx.x;
    int b = blockIdx.y;
    if (p >= 16384) return;
    int y = p >> 7, x = p & 127;
    float acc = 0.f;
#pragma unroll
    for (int ic = 0; ic < 2; ic++) {
        const float* src = mm + ((size_t)b * 2 + ic) * 16384;
        const float* wk = wsa + ic * 49;
#pragma unroll
        for (int ky = 0; ky < 7; ky++) {
            int yy = y + ky - 3;
            if ((unsigned)yy >= 128u) continue;
#pragma unroll
            for (int kx = 0; kx < 7; kx++) {
                int xx = x + kx - 3;
                if ((unsigned)xx >= 128u) continue;
                acc += src[yy * 128 + xx] * wk[ky * 7 + kx];
            }
        }
    }
    float a = (acc - bnm[0]) * rsqrtf(bnv[0] + 1e-5f) * bng[0] + bnb[0];
    sa[(size_t)b * 16384 + p] = 1.f / (1.f + expf(-a));
}

__global__ __launch_bounds__(256)
void gn_reduce_kernel(const float* __restrict__ y, float* __restrict__ stats)
{
    const int bg = blockIdx.x;
    const float* base = y + (size_t)bg * 8 * 16384;
    float s = 0.f, sq = 0.f;
    for (int i = threadIdx.x; i < 8 * 16384; i += 256) {
        float v = base[i];
        s += v;
        sq += v * v;
    }
    __shared__ float ss[256], ssq[256];
    ss[threadIdx.x] = s;
    ssq[threadIdx.x] = sq;
    __syncthreads();
    for (int st = 128; st > 0; st >>= 1) {
        if (threadIdx.x < st) {
            ss[threadIdx.x] += ss[threadIdx.x + st];
            ssq[threadIdx.x] += ssq[threadIdx.x + st];
        }
        __syncthreads();
    }
    if (threadIdx.x == 0) {
        const float inv = 1.f / (8.f * 16384.f);
        float mean = ss[0] * inv;
        float var = ssq[0] * inv - mean * mean;
        stats[bg * 2 + 0] = mean;
        stats[bg * 2 + 1] = rsqrtf(var + 1e-5f);
    }
}

__global__ __launch_bounds__(256)
void gn_apply_kernel(const float* __restrict__ y, const float* __restrict__ stats,
                     const float* __restrict__ gg, const float* __restrict__ gb,
                     float* __restrict__ out)
{
    size_t idx = (size_t)blockIdx.x * blockDim.x + threadIdx.x;
    if (idx >= (size_t)16777216) return;
    int c = (int)((idx >> 14) & 255);
    int b = (int)(idx >> 22);
    int g = c >> 3;
    float mean = stats[(b * 32 + g) * 2 + 0];
    float rstd = stats[(b * 32 + g) * 2 + 1];
    out[idx] = (y[idx] - mean) * rstd * gg[c] + gb[c];
}

// ------------------------------ host ---------------------------------------
static void* symaddr(const void* sym)
{
    void* p = nullptr;
    cudaGetSymbolAddress(&p, sym);
    return p;
}

extern "C" void kernel_launch(void* const* d_in, const int* in_sizes, int n_in,
                              void* d_out, int out_size)
{
    (void)in_sizes; (void)n_in; (void)out_size;
    const float* feat_3 = (const float*)d_in[1];
    const float* feat_4 = (const float*)d_in[2];
    const float* feat_5 = (const float*)d_in[3];
    const float* w_off5 = (const float*)d_in[4];
    const float* w_om5  = (const float*)d_in[5];
    const float* b_om5  = (const float*)d_in[6];
    const float* w_dcn5 = (const float*)d_in[7];
    const float* b_dcn5 = (const float*)d_in[8];
    const float* w_c1   = (const float*)d_in[9];
    const float* w_off4 = (const float*)d_in[10];
    const float* w_om4  = (const float*)d_in[11];
    const float* b_om4  = (const float*)d_in[12];
    const float* w_dcn4 = (const float*)d_in[13];
    const float* b_dcn4 = (const float*)d_in[14];
    const float* w_sa   = (const float*)d_in[15];
    const float* bn_g   = (const float*)d_in[16];
    const float* bn_b   = (const float*)d_in[17];
    const float* bn_m   = (const float*)d_in[18];
    const float* bn_v   = (const float*)d_in[19];
    const float* w_sem  = (const float*)d_in[20];
    const float* gn_g   = (const float*)d_in[21];
    const float* gn_b   = (const float*)d_in[22];
    float* out = (float*)d_out;

    float*    up5   = (float*)symaddr(g_up5);
    float*    om5   = (float*)symaddr(g_om5);
    unsigned* colp  = (unsigned*)symaddr(g_col);
    float*    c1b   = (float*)symaddr(g_c1b);
    float*    up4   = (float*)symaddr(g_up4);
    float*    om4   = (float*)symaddr(g_om4);
    float*    al4   = (float*)symaddr(g_al4);
    float*    f2    = (float*)symaddr(g_f2);
    float*    mm    = (float*)symaddr(g_mm);
    float*    sab   = (float*)symaddr(g_sab);
    float*    ybuf  = (float*)symaddr(g_y);
    float*    st    = (float*)symaddr(g_st);
    unsigned* f4p   = (unsigned*)symaddr(g_f4p);
    unsigned* f3p   = (unsigned*)symaddr(g_f3p);
    unsigned* up5p  = (unsigned*)symaddr(g_up5p);
    unsigned* al5p  = (unsigned*)symaddr(g_al5p);
    unsigned* up4p  = (unsigned*)symaddr(g_up4p);
    unsigned* off5p = (unsigned*)symaddr(g_off5p);
    unsigned* off4p = (unsigned*)symaddr(g_off4p);
    unsigned* f2sp  = (unsigned*)symaddr(g_f2sp);
    __nv_bfloat16* wp = (__nv_bfloat16*)symaddr(g_wp);

    cudaFuncSetAttribute(gemm_mma_kernel<0, 64>,  cudaFuncAttributeMaxDynamicSharedMemorySize, SMEM64);
    cudaFuncSetAttribute(gemm_mma_kernel<1, 64>,  cudaFuncAttributeMaxDynamicSharedMemorySize, SMEM64);
    cudaFuncSetAttribute(gemm_mma_kernel<2, 64>,  cudaFuncAttributeMaxDynamicSharedMemorySize, SMEM64);
    cudaFuncSetAttribute(gemm_mma_kernel<0, 128>, cudaFuncAttributeMaxDynamicSharedMemorySize, SMEM128);
    cudaFuncSetAttribute(gemm_mma_kernel<1, 128>, cudaFuncAttributeMaxDynamicSharedMemorySize, SMEM128);
    cudaFuncSetAttribute(gemm_mma_kernel<2, 128>, cudaFuncAttributeMaxDynamicSharedMemorySize, SMEM128);

    // weight prep (concat x2 folded into off weights)
    prep_w_kernel<<<512, 256>>>(w_off5, wp + WP_OFF5, 256, 512, 256, 2.0f);
    prep_w_kernel<<<2304, 256>>>(w_om5,  wp + WP_OM5, 216, 2304, 2304, 1.f);
    prep_w_kernel<<<2304, 256>>>(w_dcn5, wp + WP_DCN5, 256, 2304, 2304, 1.f);
    prep_w_kernel<<<512, 256>>>(w_c1,   wp + WP_C1, 256, 512, 512, 1.f);
    prep_w_kernel<<<512, 256>>>(w_off4, wp + WP_OFF4, 256, 512, 256, 2.0f);
    prep_w_kernel<<<2304, 256>>>(w_om4,  wp + WP_OM4, 216, 2304, 2304, 1.f);
    prep_w_kernel<<<2304, 256>>>(w_dcn4, wp + WP_DCN4, 256, 2304, 2304, 1.f);
    prep_w_kernel<<<512, 256>>>(w_sem,  wp + WP_SEM, 256, 512, 512, 1.f);

    // one-shot pair conversions of external inputs
    conv_pair_kernel<<<4096, 256>>>(feat_4, f4p, 4 * 256 * 1024);
    conv_pair_kernel<<<16384, 256>>>(feat_3, f3p, 4 * 256 * 4096);

    // ----- level 5 (16 -> 32), N=1024, BN=64 -----
    upsample2x_kernel<<<4096, 256>>>(feat_5, feat_5, 256, 256, 16, 16, up5, up5p);
    gemm_mma_kernel<1, 64><<<dim3(16, 2, NB), 256, SMEM64>>>(
        wp + WP_OFF5, f4p, up5p, nullptr, nullptr, off5p,
        256, 512, 1024, 256, 0, 0, 0);
    gemm_mma_kernel<2, 64><<<dim3(16, 2, NB), 256, SMEM64>>>(
        wp + WP_OM5, off5p, nullptr, b_om5, om5, nullptr,
        216, 2304, 1024, 0, 32, 32, 0);
    dcn_sample_kernel<<<(NB * 72 * 1024 + 255) / 256, 256>>>(up5, om5, colp, 32, 32);
    gemm_mma_kernel<0, 64><<<dim3(16, 2, NB), 256, SMEM64>>>(
        wp + WP_DCN5, colp, nullptr, b_dcn5, nullptr, al5p,
        256, 2304, 1024, 0, 0, 0, 1);
    gemm_mma_kernel<1, 64><<<dim3(16, 2, NB), 256, SMEM64>>>(
        wp + WP_C1, al5p, f4p, nullptr, c1b, nullptr,
        256, 512, 1024, 256, 0, 0, 0);

    // ----- level 4 (32 -> 64), N=4096, BN=128 -----
    upsample2x_kernel<<<16384, 256>>>(c1b, c1b, 256, 256, 32, 32, up4, up4p);
    gemm_mma_kernel<1, 128><<<dim3(32, 2, NB), 256, SMEM128>>>(
        wp + WP_OFF4, f3p, up4p, nullptr, nullptr, off4p,
        256, 512, 4096, 256, 0, 0, 0);
    gemm_mma_kernel<2, 128><<<dim3(32, 2, NB), 256, SMEM128>>>(
        wp + WP_OM4, off4p, nullptr, b_om4, om4, nullptr,
        216, 2304, 4096, 0, 64, 64, 0);
    dcn_sample_kernel<<<(NB * 72 * 4096 + 255) / 256, 256>>>(up4, om4, colp, 64, 64);
    gemm_mma_kernel<0, 128><<<dim3(32, 2, NB), 256, SMEM128>>>(
        wp + WP_DCN4, colp, nullptr, b_dcn4, al4, nullptr,
        256, 2304, 4096, 0, 0, 0, 1);

    // ----- feat_2 + SEM -----
    upsample2x_kernel<<<(unsigned)((4L * 512 * 16384 + 255) / 256), 256>>>(
        al4, feat_3, 256, 512, 64, 64, f2, nullptr);
    meanmax_kernel<<<dim3(64, NB), 256>>>(f2, mm);
    sa_kernel<<<dim3(64, NB), 256>>>(mm, w_sa, bn_g, bn_b, bn_m, bn_v, sab);
    f2s_kernel<<<(unsigned)((4L * 512 * 16384 + 255) / 256), 256>>>(f2, sab, f2sp);
    gemm_mma_kernel<0, 128><<<dim3(128, 2, NB), 256, SMEM128>>>(
        wp + WP_SEM, f2sp, nullptr, nullptr, ybuf, nullptr,
        256, 512, 16384, 0, 0, 0, 0);
    gn_reduce_kernel<<<128, 256>>>(ybuf, st);
    gn_apply_kernel<<<65536, 256>>>(ybuf, st, gn_g, gn_b, out);
}